// round 1
// baseline (speedup 1.0000x reference)
#include <cuda_runtime.h>
#include <cuda_bf16.h>
#include <cstddef>

// ---------------- problem constants ----------------
constexpr int NUSER = 100000;
constexpr int NITEM = 50000;
constexpr int NN    = 150000;   // total nodes
constexpr int DD    = 128;
constexpr int BB    = 3;
constexpr int LL    = 2;
constexpr int EE    = 1500000;
constexpr float BN_EPS = 1e-5f;

// ---------------- device scratch (no allocation allowed) ----------------
__device__ float g_x[(size_t)NN * DD];           // initial node features
__device__ float g_h[(size_t)NN * DD];           // current hidden
__device__ float g_agg[(size_t)NN * DD];         // aggregation / generic scratch
__device__ float g_Q[(size_t)NN * DD];           // attention query
__device__ float g_stack[(size_t)BB * NN * DD];  // per-behavior outputs
__device__ float g_cnt[(size_t)BB * NN];         // in-degree per behavior
__device__ float g_rd[(size_t)BB * NN];          // 1/max(cnt,1)
__device__ float g_logits[(size_t)NN * BB];
__device__ float g_colstat[2 * DD];              // BN column sum / sumsq
__device__ float g_bnsc[DD], g_bnsh[DD];         // BN fused scale / shift

// ---------------- small helpers ----------------
__global__ void zero_kernel(float4* p, int n4) {
    int i = blockIdx.x * blockDim.x + threadIdx.x;
    int stride = gridDim.x * blockDim.x;
    float4 z = make_float4(0.f, 0.f, 0.f, 0.f);
    for (; i < n4; i += stride) p[i] = z;
}

__global__ void zero_stats_kernel() {
    if (threadIdx.x < 2 * DD) g_colstat[threadIdx.x] = 0.f;
}

// count in-degree per (behavior, dst)
__global__ void count_kernel(const int* __restrict__ ei, const int* __restrict__ et) {
    int e = blockIdx.x * blockDim.x + threadIdx.x;
    if (e >= EE) return;
    int t = et[e];
    int d = ei[EE + e];
    atomicAdd(&g_cnt[(size_t)t * NN + d], 1.0f);
}

__global__ void rdenom_kernel() {
    int i = blockIdx.x * blockDim.x + threadIdx.x;
    if (i < BB * NN) g_rd[i] = 1.0f / fmaxf(g_cnt[i], 1.0f);
}

// one warp per edge: agg[dst] += h[src] for edges of behavior b
__global__ void scatter_kernel(const int* __restrict__ ei, const int* __restrict__ et,
                               const float* __restrict__ h, float* __restrict__ agg, int b) {
    int e = blockIdx.x * (blockDim.x >> 5) + (threadIdx.x >> 5);
    if (e >= EE) return;
    if (et[e] != b) return;
    int s = ei[e];
    int d = ei[EE + e];
    int lane = threadIdx.x & 31;
    float4 v = reinterpret_cast<const float4*>(h)[(size_t)s * 32 + lane];
    float* a = agg + (size_t)d * DD + lane * 4;
    atomicAdd(a + 0, v.x);
    atomicAdd(a + 1, v.y);
    atomicAdd(a + 2, v.z);
    atomicAdd(a + 3, v.w);
}

// ---------------- tiled GEMM: C[M,128] = rs(A)@W (+ A2@W2) + bias ----------------
// BM=64 rows/block, 256 threads as 16x16, each thread 4 rows x 8 cols (cols tx+16j).
constexpr int GEMM_AS_STRIDE = 132;                 // pad to avoid bank conflicts
constexpr int GEMM_SMEM = (64 * GEMM_AS_STRIDE + DD * DD) * 4;

__global__ __launch_bounds__(256) void gemm_kernel(
    const float* __restrict__ A, const float* __restrict__ rowscale,
    const float* __restrict__ W,
    const float* __restrict__ A2, const float* __restrict__ W2,
    const float* __restrict__ bias,
    float* __restrict__ C, int M, int relu)
{
    extern __shared__ float sm[];
    float* As = sm;
    float* Ws = sm + 64 * GEMM_AS_STRIDE;
    int tid = threadIdx.x;
    int tx = tid & 15, ty = tid >> 4;
    int row0 = blockIdx.x * 64;

    float acc[4][8];
#pragma unroll
    for (int i = 0; i < 4; i++)
#pragma unroll
        for (int j = 0; j < 8; j++) acc[i][j] = 0.f;

    for (int pass = 0; pass < 2; ++pass) {
        const float* Ap = pass ? A2 : A;
        const float* Wp = pass ? W2 : W;
        if (Ap == nullptr) break;

        // load W tile: 128x128 floats = 4096 float4
#pragma unroll
        for (int i = 0; i < 16; ++i) {
            int idx = tid + i * 256;
            reinterpret_cast<float4*>(Ws)[idx] = reinterpret_cast<const float4*>(Wp)[idx];
        }
        // load A tile: 64x128 floats = 2048 float4 (row-scaled on pass 0 if requested)
#pragma unroll
        for (int i = 0; i < 8; ++i) {
            int idx = tid + i * 256;
            int r = idx >> 5, c4 = idx & 31;
            int gr = row0 + r;
            float4 v = make_float4(0.f, 0.f, 0.f, 0.f);
            if (gr < M) {
                v = reinterpret_cast<const float4*>(Ap)[(size_t)gr * 32 + c4];
                if (pass == 0 && rowscale != nullptr) {
                    float srs = rowscale[gr];
                    v.x *= srs; v.y *= srs; v.z *= srs; v.w *= srs;
                }
            }
            *reinterpret_cast<float4*>(As + r * GEMM_AS_STRIDE + c4 * 4) = v;
        }
        __syncthreads();

#pragma unroll 16
        for (int k = 0; k < DD; ++k) {
            float a[4], w[8];
#pragma unroll
            for (int i = 0; i < 4; i++) a[i] = As[(ty * 4 + i) * GEMM_AS_STRIDE + k];
#pragma unroll
            for (int j = 0; j < 8; j++) w[j] = Ws[k * DD + tx + j * 16];
#pragma unroll
            for (int i = 0; i < 4; i++)
#pragma unroll
                for (int j = 0; j < 8; j++) acc[i][j] = fmaf(a[i], w[j], acc[i][j]);
        }
        __syncthreads();
    }

#pragma unroll
    for (int i = 0; i < 4; i++) {
        int gr = row0 + ty * 4 + i;
        if (gr >= M) continue;
#pragma unroll
        for (int j = 0; j < 8; j++) {
            int col = tx + j * 16;
            float o = acc[i][j] + (bias ? bias[col] : 0.f);
            if (relu) o = fmaxf(o, 0.f);
            C[(size_t)gr * DD + col] = o;
        }
    }
}

// ---------------- BatchNorm ----------------
constexpr int BN_CHUNK = 147;   // rows per block; grid = ceil(NN/147)

__global__ void bn_stats_kernel(const float* __restrict__ h) {
    __shared__ float ssum[256], ssq[256];
    int col = threadIdx.x & 127;
    int half = threadIdx.x >> 7;
    int r0 = blockIdx.x * BN_CHUNK;
    int r1 = r0 + BN_CHUNK; if (r1 > NN) r1 = NN;
    float s = 0.f, q = 0.f;
    for (int r = r0 + half; r < r1; r += 2) {
        float v = h[(size_t)r * DD + col];
        s += v; q += v * v;
    }
    ssum[threadIdx.x] = s; ssq[threadIdx.x] = q;
    __syncthreads();
    if (half == 0) {
        atomicAdd(&g_colstat[col], ssum[col] + ssum[col + 128]);
        atomicAdd(&g_colstat[DD + col], ssq[col] + ssq[col + 128]);
    }
}

__global__ void bn_finalize_kernel(const float* __restrict__ gamma, const float* __restrict__ beta) {
    int c = threadIdx.x;
    if (c >= DD) return;
    float mu = g_colstat[c] * (1.0f / NN);
    float var = g_colstat[DD + c] * (1.0f / NN) - mu * mu;
    float sc = gamma[c] * rsqrtf(var + BN_EPS);
    g_bnsc[c] = sc;
    g_bnsh[c] = beta[c] - mu * sc;
}

// mode 0: h = relu(norm(h)) in place.  mode 1: outstack = x + norm(h)
__global__ void bn_apply_kernel(float* __restrict__ h, const float* __restrict__ x,
                                float* __restrict__ outstack, int mode) {
    int idx = blockIdx.x * blockDim.x + threadIdx.x;       // over NN*32 float4s
    if (idx >= NN * 32) return;
    int c4 = (idx & 31) * 4;
    float4 v = reinterpret_cast<float4*>(h)[idx];
    float4 o;
    o.x = v.x * g_bnsc[c4 + 0] + g_bnsh[c4 + 0];
    o.y = v.y * g_bnsc[c4 + 1] + g_bnsh[c4 + 1];
    o.z = v.z * g_bnsc[c4 + 2] + g_bnsh[c4 + 2];
    o.w = v.w * g_bnsc[c4 + 3] + g_bnsh[c4 + 3];
    if (mode == 0) {
        o.x = fmaxf(o.x, 0.f); o.y = fmaxf(o.y, 0.f);
        o.z = fmaxf(o.z, 0.f); o.w = fmaxf(o.w, 0.f);
        reinterpret_cast<float4*>(h)[idx] = o;
    } else {
        float4 xv = reinterpret_cast<const float4*>(x)[idx];
        o.x += xv.x; o.y += xv.y; o.z += xv.z; o.w += xv.w;
        reinterpret_cast<float4*>(outstack)[idx] = o;
    }
}

// ---------------- attention ----------------
// one warp per node: logits[n,b] = dot(Q[n], K[n])
__global__ void dot_kernel(const float* __restrict__ Q, const float* __restrict__ K,
                           float* __restrict__ logits, int b) {
    int n = blockIdx.x * (blockDim.x >> 5) + (threadIdx.x >> 5);
    if (n >= NN) return;
    int lane = threadIdx.x & 31;
    float4 q = reinterpret_cast<const float4*>(Q)[(size_t)n * 32 + lane];
    float4 k = reinterpret_cast<const float4*>(K)[(size_t)n * 32 + lane];
    float p = q.x * k.x + q.y * k.y + q.z * k.z + q.w * k.w;
#pragma unroll
    for (int o = 16; o; o >>= 1) p += __shfl_xor_sync(0xFFFFFFFFu, p, o);
    if (lane == 0) logits[(size_t)n * BB + b] = p;
}

__global__ void softmax_fuse_kernel(const float* __restrict__ logits,
                                    const float* __restrict__ stack,
                                    float* __restrict__ out) {
    int idx = blockIdx.x * blockDim.x + threadIdx.x;   // over NN*32 float4s
    if (idx >= NN * 32) return;
    int n = idx >> 5;
    float l0 = logits[(size_t)n * 3 + 0];
    float l1 = logits[(size_t)n * 3 + 1];
    float l2 = logits[(size_t)n * 3 + 2];
    float m = fmaxf(l0, fmaxf(l1, l2));
    float e0 = __expf(l0 - m), e1 = __expf(l1 - m), e2 = __expf(l2 - m);
    float inv = 1.0f / (e0 + e1 + e2);
    float w0 = e0 * inv, w1 = e1 * inv, w2 = e2 * inv;
    float4 s0 = reinterpret_cast<const float4*>(stack)[idx];
    float4 s1 = reinterpret_cast<const float4*>(stack + (size_t)NN * DD)[idx];
    float4 s2 = reinterpret_cast<const float4*>(stack + (size_t)2 * NN * DD)[idx];
    float4 o;
    o.x = w0 * s0.x + w1 * s1.x + w2 * s2.x;
    o.y = w0 * s0.y + w1 * s1.y + w2 * s2.y;
    o.z = w0 * s0.z + w1 * s1.z + w2 * s2.z;
    o.w = w0 * s0.w + w1 * s1.w + w2 * s2.w;
    reinterpret_cast<float4*>(out)[idx] = o;
}

// ---------------- host launch ----------------
static inline int gblk(int m) { return (m + 63) / 64; }

extern "C" void kernel_launch(void* const* d_in, const int* in_sizes, int n_in,
                              void* d_out, int out_size) {
    const int*   ei          = (const int*)d_in[0];    // edge_index [2,E]
    const int*   et          = (const int*)d_in[1];    // edge_type [E]
    const float* item_feats  = (const float*)d_in[2];
    const float* user_emb    = (const float*)d_in[3];
    const float* user_proj_W = (const float*)d_in[4];
    const float* user_proj_b = (const float*)d_in[5];
    const float* item_proj_W = (const float*)d_in[6];
    const float* item_proj_b = (const float*)d_in[7];
    const float* sage_Wl     = (const float*)d_in[8];  // [B,L,D,D]
    const float* sage_bl     = (const float*)d_in[9];  // [B,L,D]
    const float* sage_Wr     = (const float*)d_in[10]; // [B,L,D,D]
    const float* bn_gamma    = (const float*)d_in[11]; // [B,L,D]
    const float* bn_beta     = (const float*)d_in[12];
    const float* query_W     = (const float*)d_in[13];
    const float* query_b     = (const float*)d_in[14];
    const float* key_W       = (const float*)d_in[15]; // [B,D,D]
    const float* key_b       = (const float*)d_in[16]; // [B,D]
    const float* fuse_W      = (const float*)d_in[17];
    const float* fuse_b      = (const float*)d_in[18];
    const float* refine_W    = (const float*)d_in[19];
    const float* refine_b    = (const float*)d_in[20];
    float* out = (float*)d_out;
    (void)in_sizes; (void)n_in; (void)out_size;

    float *px, *ph, *pagg, *pQ, *pstack, *pcnt, *prd, *plog;
    cudaGetSymbolAddress((void**)&px,     g_x);
    cudaGetSymbolAddress((void**)&ph,     g_h);
    cudaGetSymbolAddress((void**)&pagg,   g_agg);
    cudaGetSymbolAddress((void**)&pQ,     g_Q);
    cudaGetSymbolAddress((void**)&pstack, g_stack);
    cudaGetSymbolAddress((void**)&pcnt,   g_cnt);
    cudaGetSymbolAddress((void**)&prd,    g_rd);
    cudaGetSymbolAddress((void**)&plog,   g_logits);

    cudaFuncSetAttribute(gemm_kernel, cudaFuncAttributeMaxDynamicSharedMemorySize, GEMM_SMEM);

    const int NV4 = NN * 32;                     // float4 count of an [N,D] buffer
    const int APPLY_GRID = (NV4 + 255) / 256;

    // degrees
    zero_kernel<<<2048, 256>>>((float4*)pcnt, (BB * NN) / 4);
    count_kernel<<<(EE + 255) / 256, 256>>>(ei, et);
    rdenom_kernel<<<(BB * NN + 255) / 256, 256>>>();

    // initial features x = [user_emb@Wu + bu ; item_feats@Wi + bi]
    gemm_kernel<<<gblk(NUSER), 256, GEMM_SMEM>>>(user_emb, nullptr, user_proj_W,
                                                 nullptr, nullptr, user_proj_b, px, NUSER, 0);
    gemm_kernel<<<gblk(NITEM), 256, GEMM_SMEM>>>(item_feats, nullptr, item_proj_W,
                                                 nullptr, nullptr, item_proj_b,
                                                 px + (size_t)NUSER * DD, NITEM, 0);

    const int BN_GRID = (NN + BN_CHUNK - 1) / BN_CHUNK;

    for (int b = 0; b < BB; ++b) {
        const float* hin = px;
        for (int l = 0; l < LL; ++l) {
            int bl = b * LL + l;
            zero_kernel<<<4096, 256>>>((float4*)pagg, NV4);
            scatter_kernel<<<(EE + 7) / 8, 256>>>(ei, et, hin, pagg, b);
            // h = (agg/denom)@Wl + h@Wr + bl
            gemm_kernel<<<gblk(NN), 256, GEMM_SMEM>>>(pagg, prd + (size_t)b * NN,
                                                      sage_Wl + (size_t)bl * DD * DD,
                                                      hin, sage_Wr + (size_t)bl * DD * DD,
                                                      sage_bl + (size_t)bl * DD, ph, NN, 0);
            zero_stats_kernel<<<1, 256>>>();
            bn_stats_kernel<<<BN_GRID, 256>>>(ph);
            bn_finalize_kernel<<<1, 128>>>(bn_gamma + (size_t)bl * DD, bn_beta + (size_t)bl * DD);
            if (l < LL - 1) {
                bn_apply_kernel<<<APPLY_GRID, 256>>>(ph, px, nullptr, 0);       // relu in place
            } else {
                bn_apply_kernel<<<APPLY_GRID, 256>>>(ph, px,
                                                     pstack + (size_t)b * NN * DD, 1); // residual
            }
            hin = ph;
        }
    }

    // attention fusion
    gemm_kernel<<<gblk(NN), 256, GEMM_SMEM>>>(px, nullptr, query_W,
                                              nullptr, nullptr, query_b, pQ, NN, 0);
    for (int b = 0; b < BB; ++b) {
        gemm_kernel<<<gblk(NN), 256, GEMM_SMEM>>>(pstack + (size_t)b * NN * DD, nullptr,
                                                  key_W + (size_t)b * DD * DD,
                                                  nullptr, nullptr, key_b + (size_t)b * DD,
                                                  pagg, NN, 0);
        dot_kernel<<<(NN + 7) / 8, 256>>>(pQ, pagg, plog, b);
    }
    softmax_fuse_kernel<<<APPLY_GRID, 256>>>(plog, pstack, ph);

    gemm_kernel<<<gblk(NN), 256, GEMM_SMEM>>>(ph, nullptr, fuse_W,
                                              nullptr, nullptr, fuse_b, pagg, NN, 0);
    gemm_kernel<<<gblk(NN), 256, GEMM_SMEM>>>(pagg, nullptr, refine_W,
                                              nullptr, nullptr, refine_b, out, NN, 1);
}

// round 4
// speedup vs baseline: 1.1532x; 1.1532x over previous
#include <cuda_runtime.h>
#include <cuda_bf16.h>
#include <cstddef>

// ---------------- problem constants ----------------
constexpr int NUSER = 100000;
constexpr int NITEM = 50000;
constexpr int NN    = 150000;   // total nodes
constexpr int DD    = 128;
constexpr int BB    = 3;
constexpr int LL    = 2;
constexpr int EE    = 1500000;
constexpr float BN_EPS = 1e-5f;

typedef unsigned long long ull;

// ---------------- device scratch (no allocation allowed) ----------------
__device__ float g_x[(size_t)NN * DD];           // initial node features
__device__ float g_h[(size_t)NN * DD];           // current hidden
__device__ float g_agg[(size_t)NN * DD];         // aggregation scratch
__device__ float g_Q[(size_t)NN * DD];           // attention query
__device__ float g_stack[(size_t)BB * NN * DD];  // per-behavior outputs
__device__ float g_cnt[(size_t)BB * NN];         // in-degree per behavior
__device__ float g_rd[(size_t)BB * NN];          // 1/max(cnt,1)
__device__ float g_logits[(size_t)NN * BB];
__device__ float g_colstat[2 * DD];              // BN column sum / sumsq
__device__ float g_bnsc[DD], g_bnsh[DD];         // BN fused scale / shift
__device__ float g_Wc[DD * DD];                  // fuse_W @ refine_W
__device__ float g_bc[DD];                       // fuse_b @ refine_W + refine_b
__device__ int   g_tcnt[BB];                     // edges per behavior
__device__ int   g_eoff[BB + 1];                 // bucket offsets
__device__ int   g_ecur[BB];                     // bucket cursors
__device__ int   g_bsrc[EE];                     // bucketed src
__device__ int   g_bdst[EE];                     // bucketed dst

// ---------------- f32x2 packed-FMA helpers ----------------
#define FFMA2(d, a, b) \
    asm("fma.rn.f32x2 %0, %1, %2, %3;" : "=l"(d) : "l"(a), "l"(b), "l"(d))
#define PACKDUP(d, f) do { unsigned _u = __float_as_uint(f); \
    asm("mov.b64 %0, {%1, %2};" : "=l"(d) : "r"(_u), "r"(_u)); } while (0)
#define UNPK(lo, hi, d) do { unsigned _l, _h; \
    asm("mov.b64 {%0, %1}, %2;" : "=r"(_l), "=r"(_h) : "l"(d)); \
    lo = __uint_as_float(_l); hi = __uint_as_float(_h); } while (0)

// ---------------- small helpers ----------------
__global__ void zero_kernel(float4* p, int n4) {
    int i = blockIdx.x * blockDim.x + threadIdx.x;
    int stride = gridDim.x * blockDim.x;
    float4 z = make_float4(0.f, 0.f, 0.f, 0.f);
    for (; i < n4; i += stride) p[i] = z;
}

__global__ void zero_small_kernel() {          // stats + bucket counters
    int t = threadIdx.x;
    if (t < 2 * DD) g_colstat[t] = 0.f;
    if (t < BB) g_tcnt[t] = 0;
}

__global__ void zero_stats_kernel() {
    if (threadIdx.x < 2 * DD) g_colstat[threadIdx.x] = 0.f;
}

// degree count per (behavior, dst) + per-type histogram
__global__ void count_kernel(const int* __restrict__ ei, const int* __restrict__ et) {
    __shared__ int sc[BB];
    if (threadIdx.x < BB) sc[threadIdx.x] = 0;
    __syncthreads();
    int e = blockIdx.x * blockDim.x + threadIdx.x;
    if (e < EE) {
        int t = et[e];
        int d = ei[EE + e];
        atomicAdd(&g_cnt[(size_t)t * NN + d], 1.0f);
        atomicAdd(&sc[t], 1);
    }
    __syncthreads();
    if (threadIdx.x < BB) atomicAdd(&g_tcnt[threadIdx.x], sc[threadIdx.x]);
}

__global__ void offsets_kernel() {
    if (threadIdx.x == 0) {
        int acc = 0;
        g_eoff[0] = 0;
        for (int b = 0; b < BB; ++b) { acc += g_tcnt[b]; g_eoff[b + 1] = acc; g_ecur[b] = g_eoff[b]; }
    }
}

__global__ void rdenom_kernel() {
    int i = blockIdx.x * blockDim.x + threadIdx.x;
    if (i < BB * NN) g_rd[i] = 1.0f / fmaxf(g_cnt[i], 1.0f);
}

// warp-aggregated bucketing of edges by behavior
__global__ void bucket_kernel(const int* __restrict__ ei, const int* __restrict__ et) {
    int e = blockIdx.x * blockDim.x + threadIdx.x;
    int lane = threadIdx.x & 31;
    int t = (e < EE) ? et[e] : -1;
#pragma unroll
    for (int b = 0; b < BB; ++b) {
        unsigned m = __ballot_sync(0xFFFFFFFFu, t == b);
        if (!m) continue;
        int leader = __ffs(m) - 1;
        int base = 0;
        if (lane == leader) base = atomicAdd(&g_ecur[b], __popc(m));
        base = __shfl_sync(0xFFFFFFFFu, base, leader);
        if (t == b) {
            int pos = base + __popc(m & ((1u << lane) - 1));
            g_bsrc[pos] = ei[e];
            g_bdst[pos] = ei[EE + e];
        }
    }
}

// persistent warps: agg[dst] += h[src] over bucketed range of behavior b
__global__ void scatter_kernel(const float* __restrict__ h, float* __restrict__ agg, int b) {
    int nwarp = gridDim.x * (blockDim.x >> 5);
    int w = blockIdx.x * (blockDim.x >> 5) + (threadIdx.x >> 5);
    int lane = threadIdx.x & 31;
    int lo = g_eoff[b], hi = g_eoff[b + 1];
    for (int e = lo + w; e < hi; e += nwarp) {
        int s = g_bsrc[e];
        int d = g_bdst[e];
        float4 v = reinterpret_cast<const float4*>(h)[(size_t)s * 32 + lane];
        float* a = agg + (size_t)d * DD + lane * 4;
        atomicAdd(a + 0, v.x);
        atomicAdd(a + 1, v.y);
        atomicAdd(a + 2, v.z);
        atomicAdd(a + 3, v.w);
    }
}

// ---------------- FFMA2 tiled GEMM ----------------
// C[M,128] = rs(A)@W (+ A2@W2) + bias, optional relu.
// Optional fused epilogues: BN column stats (do_colstat) or Q-dot logits (Qdot).
// 256 threads (tx=tid&15, ty=tid>>4); block = 64 rows; thread = 4 rows x 8 cols
// (cols tx*4..+3 and 64+tx*4..+3). smem: AsT[128][64] transposed A + Ws[128][128].
constexpr int GEMM_SMEM = (128 * 64 + 128 * 128) * 4;   // 96 KB

__global__ __launch_bounds__(256) void gemm_kernel(
    const float* __restrict__ A, const float* __restrict__ rowscale,
    const float* __restrict__ W,
    const float* __restrict__ A2, const float* __restrict__ W2,
    const float* __restrict__ bias,
    float* __restrict__ C, int M, int relu, int do_colstat,
    const float* __restrict__ Qdot, float* __restrict__ logits, int bidx)
{
    extern __shared__ float sm[];
    float* AsT = sm;                 // [128][64] k-major
    float* Ws  = sm + 128 * 64;      // [128][128]
    int tid = threadIdx.x;
    int tx = tid & 15, ty = tid >> 4;
    int row0 = blockIdx.x * 64;

    ull acc[4][4];
#pragma unroll
    for (int i = 0; i < 4; i++)
#pragma unroll
        for (int p = 0; p < 4; p++) acc[i][p] = 0ull;

    for (int pass = 0; pass < 2; ++pass) {
        const float* Ap = pass ? A2 : A;
        const float* Wp = pass ? W2 : W;
        if (Ap == nullptr) break;
        if (pass) __syncthreads();   // finish reading previous tiles

        // load W tile (coalesced, conflict-free STS.128)
#pragma unroll
        for (int i = 0; i < 16; ++i) {
            int idx = tid + i * 256;
            reinterpret_cast<float4*>(Ws)[idx] = reinterpret_cast<const float4*>(Wp)[idx];
        }
        // load A tile transposed: thread (i) handles row r=idx&63, cols c4*4..+3
#pragma unroll
        for (int i = 0; i < 8; ++i) {
            int idx = tid + i * 256;
            int r = idx & 63, c4 = idx >> 6;     // c4 in 0..31
            int gr = row0 + r;
            float4 v = make_float4(0.f, 0.f, 0.f, 0.f);
            if (gr < M) {
                v = reinterpret_cast<const float4*>(Ap)[(size_t)gr * 32 + c4];
                if (pass == 0 && rowscale != nullptr) {
                    float srs = rowscale[gr];
                    v.x *= srs; v.y *= srs; v.z *= srs; v.w *= srs;
                }
            }
            int c = c4 * 4;
            AsT[(c + 0) * 64 + r] = v.x;
            AsT[(c + 1) * 64 + r] = v.y;
            AsT[(c + 2) * 64 + r] = v.z;
            AsT[(c + 3) * 64 + r] = v.w;
        }
        __syncthreads();

#pragma unroll 8
        for (int k = 0; k < DD; ++k) {
            ulonglong2 w0 = *reinterpret_cast<const ulonglong2*>(Ws + k * 128 + tx * 4);
            ulonglong2 w1 = *reinterpret_cast<const ulonglong2*>(Ws + k * 128 + 64 + tx * 4);
            float4 av = *reinterpret_cast<const float4*>(AsT + k * 64 + ty * 4);
            ull aa0, aa1, aa2, aa3;
            PACKDUP(aa0, av.x); PACKDUP(aa1, av.y);
            PACKDUP(aa2, av.z); PACKDUP(aa3, av.w);
            FFMA2(acc[0][0], aa0, w0.x); FFMA2(acc[0][1], aa0, w0.y);
            FFMA2(acc[0][2], aa0, w1.x); FFMA2(acc[0][3], aa0, w1.y);
            FFMA2(acc[1][0], aa1, w0.x); FFMA2(acc[1][1], aa1, w0.y);
            FFMA2(acc[1][2], aa1, w1.x); FFMA2(acc[1][3], aa1, w1.y);
            FFMA2(acc[2][0], aa2, w0.x); FFMA2(acc[2][1], aa2, w0.y);
            FFMA2(acc[2][2], aa2, w1.x); FFMA2(acc[2][3], aa2, w1.y);
            FFMA2(acc[3][0], aa3, w0.x); FFMA2(acc[3][1], aa3, w0.y);
            FFMA2(acc[3][2], aa3, w1.x); FFMA2(acc[3][3], aa3, w1.y);
        }
    }
    __syncthreads();   // smem free for epilogue reuse

    // unpack + bias + relu
    float out[4][8];
    float4 b0 = make_float4(0.f, 0.f, 0.f, 0.f), b1 = b0;
    if (bias) {
        b0 = reinterpret_cast<const float4*>(bias)[tx];
        b1 = reinterpret_cast<const float4*>(bias)[16 + tx];
    }
#pragma unroll
    for (int i = 0; i < 4; i++) {
        UNPK(out[i][0], out[i][1], acc[i][0]);
        UNPK(out[i][2], out[i][3], acc[i][1]);
        UNPK(out[i][4], out[i][5], acc[i][2]);
        UNPK(out[i][6], out[i][7], acc[i][3]);
        out[i][0] += b0.x; out[i][1] += b0.y; out[i][2] += b0.z; out[i][3] += b0.w;
        out[i][4] += b1.x; out[i][5] += b1.y; out[i][6] += b1.z; out[i][7] += b1.w;
        if (relu)
#pragma unroll
            for (int j = 0; j < 8; j++) out[i][j] = fmaxf(out[i][j], 0.f);
    }

    if (C) {
#pragma unroll
        for (int i = 0; i < 4; i++) {
            int gr = row0 + ty * 4 + i;
            if (gr >= M) continue;
            float4 lo = make_float4(out[i][0], out[i][1], out[i][2], out[i][3]);
            float4 hi = make_float4(out[i][4], out[i][5], out[i][6], out[i][7]);
            reinterpret_cast<float4*>(C)[(size_t)gr * 32 + tx] = lo;
            reinterpret_cast<float4*>(C)[(size_t)gr * 32 + 16 + tx] = hi;
        }
    }

    if (do_colstat) {
        float* sc = sm;           // 256 floats: [0..127]=sum, [128..255]=sumsq
        sc[tid] = 0.f;
        __syncthreads();
#pragma unroll
        for (int j = 0; j < 8; j++) {
            int col = (j < 4) ? (tx * 4 + j) : (64 + tx * 4 + (j - 4));
            float s = 0.f, q = 0.f;
#pragma unroll
            for (int i = 0; i < 4; i++) {
                int gr = row0 + ty * 4 + i;
                if (gr < M) { float v = out[i][j]; s += v; q += v * v; }
            }
            atomicAdd(&sc[col], s);
            atomicAdd(&sc[128 + col], q);
        }
        __syncthreads();
        if (tid < 128) {
            atomicAdd(&g_colstat[tid], sc[tid]);
            atomicAdd(&g_colstat[128 + tid], sc[128 + tid]);
        }
    }

    if (Qdot) {
        float* sd = sm;           // [64][16]
#pragma unroll
        for (int i = 0; i < 4; i++) {
            int gr = row0 + ty * 4 + i;
            float p = 0.f;
            if (gr < M) {
                float4 q0 = reinterpret_cast<const float4*>(Qdot)[(size_t)gr * 32 + tx];
                float4 q1 = reinterpret_cast<const float4*>(Qdot)[(size_t)gr * 32 + 16 + tx];
                p = out[i][0] * q0.x + out[i][1] * q0.y + out[i][2] * q0.z + out[i][3] * q0.w
                  + out[i][4] * q1.x + out[i][5] * q1.y + out[i][6] * q1.z + out[i][7] * q1.w;
            }
            sd[(ty * 4 + i) * 16 + tx] = p;
        }
        __syncthreads();
        if (tid < 64) {
            float s = 0.f;
#pragma unroll
            for (int j = 0; j < 16; j++) s += sd[tid * 16 + j];
            int gr = row0 + tid;
            if (gr < M) logits[(size_t)gr * BB + bidx] = s;
        }
    }
}

// ---------------- BatchNorm finalize / apply ----------------
__global__ void bn_finalize_kernel(const float* __restrict__ gamma, const float* __restrict__ beta) {
    int c = threadIdx.x;
    if (c >= DD) return;
    float mu = g_colstat[c] * (1.0f / NN);
    float var = g_colstat[DD + c] * (1.0f / NN) - mu * mu;
    float sc = gamma[c] * rsqrtf(var + BN_EPS);
    g_bnsc[c] = sc;
    g_bnsh[c] = beta[c] - mu * sc;
}

// mode 0: h = relu(norm(h)) in place.  mode 1: outstack = x + norm(h)
__global__ void bn_apply_kernel(float* __restrict__ h, const float* __restrict__ x,
                                float* __restrict__ outstack, int mode) {
    int idx = blockIdx.x * blockDim.x + threadIdx.x;       // over NN*32 float4s
    if (idx >= NN * 32) return;
    int c4 = (idx & 31) * 4;
    float4 v = reinterpret_cast<float4*>(h)[idx];
    float4 o;
    o.x = v.x * g_bnsc[c4 + 0] + g_bnsh[c4 + 0];
    o.y = v.y * g_bnsc[c4 + 1] + g_bnsh[c4 + 1];
    o.z = v.z * g_bnsc[c4 + 2] + g_bnsh[c4 + 2];
    o.w = v.w * g_bnsc[c4 + 3] + g_bnsh[c4 + 3];
    if (mode == 0) {
        o.x = fmaxf(o.x, 0.f); o.y = fmaxf(o.y, 0.f);
        o.z = fmaxf(o.z, 0.f); o.w = fmaxf(o.w, 0.f);
        reinterpret_cast<float4*>(h)[idx] = o;
    } else {
        float4 xv = reinterpret_cast<const float4*>(x)[idx];
        o.x += xv.x; o.y += xv.y; o.z += xv.z; o.w += xv.w;
        reinterpret_cast<float4*>(outstack)[idx] = o;
    }
}

// ---------------- softmax + weighted fuse ----------------
__global__ void softmax_fuse_kernel(const float* __restrict__ logits,
                                    const float* __restrict__ stack,
                                    float* __restrict__ out) {
    int idx = blockIdx.x * blockDim.x + threadIdx.x;   // over NN*32 float4s
    if (idx >= NN * 32) return;
    int n = idx >> 5;
    float l0 = logits[(size_t)n * 3 + 0];
    float l1 = logits[(size_t)n * 3 + 1];
    float l2 = logits[(size_t)n * 3 + 2];
    float m = fmaxf(l0, fmaxf(l1, l2));
    float e0 = __expf(l0 - m), e1 = __expf(l1 - m), e2 = __expf(l2 - m);
    float inv = 1.0f / (e0 + e1 + e2);
    float w0 = e0 * inv, w1 = e1 * inv, w2 = e2 * inv;
    float4 s0 = reinterpret_cast<const float4*>(stack)[idx];
    float4 s1 = reinterpret_cast<const float4*>(stack + (size_t)NN * DD)[idx];
    float4 s2 = reinterpret_cast<const float4*>(stack + (size_t)2 * NN * DD)[idx];
    float4 o;
    o.x = w0 * s0.x + w1 * s1.x + w2 * s2.x;
    o.y = w0 * s0.y + w1 * s1.y + w2 * s2.y;
    o.z = w0 * s0.z + w1 * s1.z + w2 * s2.z;
    o.w = w0 * s0.w + w1 * s1.w + w2 * s2.w;
    reinterpret_cast<float4*>(out)[idx] = o;
}

// bc = fuse_b @ refine_W + refine_b
__global__ void bias_combine_kernel(const float* __restrict__ fuse_b,
                                    const float* __restrict__ refine_W,
                                    const float* __restrict__ refine_b) {
    int c = threadIdx.x;
    if (c >= DD) return;
    float s = refine_b[c];
    for (int k = 0; k < DD; ++k) s += fuse_b[k] * refine_W[k * DD + c];
    g_bc[c] = s;
}

// ---------------- host launch ----------------
static inline int gblk(int m) { return (m + 63) / 64; }

extern "C" void kernel_launch(void* const* d_in, const int* in_sizes, int n_in,
                              void* d_out, int out_size) {
    const int*   ei          = (const int*)d_in[0];    // edge_index [2,E]
    const int*   et          = (const int*)d_in[1];    // edge_type [E]
    const float* item_feats  = (const float*)d_in[2];
    const float* user_emb    = (const float*)d_in[3];
    const float* user_proj_W = (const float*)d_in[4];
    const float* user_proj_b = (const float*)d_in[5];
    const float* item_proj_W = (const float*)d_in[6];
    const float* item_proj_b = (const float*)d_in[7];
    const float* sage_Wl     = (const float*)d_in[8];  // [B,L,D,D]
    const float* sage_bl     = (const float*)d_in[9];  // [B,L,D]
    const float* sage_Wr     = (const float*)d_in[10]; // [B,L,D,D]
    const float* bn_gamma    = (const float*)d_in[11]; // [B,L,D]
    const float* bn_beta     = (const float*)d_in[12];
    const float* query_W     = (const float*)d_in[13];
    const float* query_b     = (const float*)d_in[14];
    const float* key_W       = (const float*)d_in[15]; // [B,D,D]
    const float* key_b       = (const float*)d_in[16]; // [B,D]
    const float* fuse_W      = (const float*)d_in[17];
    const float* fuse_b      = (const float*)d_in[18];
    const float* refine_W    = (const float*)d_in[19];
    const float* refine_b    = (const float*)d_in[20];
    float* out = (float*)d_out;
    (void)in_sizes; (void)n_in; (void)out_size;

    float *px, *ph, *pagg, *pQ, *pstack, *pcnt, *prd, *plog, *pWc, *pbc;
    cudaGetSymbolAddress((void**)&px,     g_x);
    cudaGetSymbolAddress((void**)&ph,     g_h);
    cudaGetSymbolAddress((void**)&pagg,   g_agg);
    cudaGetSymbolAddress((void**)&pQ,     g_Q);
    cudaGetSymbolAddress((void**)&pstack, g_stack);
    cudaGetSymbolAddress((void**)&pcnt,   g_cnt);
    cudaGetSymbolAddress((void**)&prd,    g_rd);
    cudaGetSymbolAddress((void**)&plog,   g_logits);
    cudaGetSymbolAddress((void**)&pWc,    g_Wc);
    cudaGetSymbolAddress((void**)&pbc,    g_bc);

    cudaFuncSetAttribute(gemm_kernel, cudaFuncAttributeMaxDynamicSharedMemorySize, GEMM_SMEM);

    const int NV4 = NN * 32;
    const int APPLY_GRID = (NV4 + 255) / 256;

    // edge preprocessing: degrees + type buckets
    zero_kernel<<<512, 256>>>((float4*)pcnt, (BB * NN) / 4);
    zero_small_kernel<<<1, 256>>>();
    count_kernel<<<(EE + 255) / 256, 256>>>(ei, et);
    offsets_kernel<<<1, 32>>>();
    rdenom_kernel<<<(BB * NN + 255) / 256, 256>>>();
    bucket_kernel<<<(EE + 255) / 256, 256>>>(ei, et);

    // precombine fuse+refine (no nonlinearity between them)
    gemm_kernel<<<gblk(DD), 256, GEMM_SMEM>>>(fuse_W, nullptr, refine_W,
        nullptr, nullptr, nullptr, pWc, DD, 0, 0, nullptr, nullptr, 0);
    bias_combine_kernel<<<1, 128>>>(fuse_b, refine_W, refine_b);

    // initial features x = [user_emb@Wu + bu ; item_feats@Wi + bi]
    gemm_kernel<<<gblk(NUSER), 256, GEMM_SMEM>>>(user_emb, nullptr, user_proj_W,
        nullptr, nullptr, user_proj_b, px, NUSER, 0, 0, nullptr, nullptr, 0);
    gemm_kernel<<<gblk(NITEM), 256, GEMM_SMEM>>>(item_feats, nullptr, item_proj_W,
        nullptr, nullptr, item_proj_b, px + (size_t)NUSER * DD, NITEM, 0, 0, nullptr, nullptr, 0);

    for (int b = 0; b < BB; ++b) {
        const float* hin = px;
        for (int l = 0; l < LL; ++l) {
            int bl = b * LL + l;
            zero_kernel<<<4096, 256>>>((float4*)pagg, NV4);
            scatter_kernel<<<1184, 256>>>(hin, pagg, b);
            zero_stats_kernel<<<1, 256>>>();
            // h = (agg/denom)@Wl + h@Wr + bl   (+ fused BN column stats)
            gemm_kernel<<<gblk(NN), 256, GEMM_SMEM>>>(pagg, prd + (size_t)b * NN,
                sage_Wl + (size_t)bl * DD * DD, hin, sage_Wr + (size_t)bl * DD * DD,
                sage_bl + (size_t)bl * DD, ph, NN, 0, 1, nullptr, nullptr, 0);
            bn_finalize_kernel<<<1, 128>>>(bn_gamma + (size_t)bl * DD, bn_beta + (size_t)bl * DD);
            if (l < LL - 1) {
                bn_apply_kernel<<<APPLY_GRID, 256>>>(ph, px, nullptr, 0);       // relu in place
            } else {
                bn_apply_kernel<<<APPLY_GRID, 256>>>(ph, px,
                    pstack + (size_t)b * NN * DD, 1);                            // residual
            }
            hin = ph;
        }
    }

    // attention: Q, then K-GEMMs with fused Q-dot (no K materialization)
    gemm_kernel<<<gblk(NN), 256, GEMM_SMEM>>>(px, nullptr, query_W,
        nullptr, nullptr, query_b, pQ, NN, 0, 0, nullptr, nullptr, 0);
    for (int b = 0; b < BB; ++b) {
        gemm_kernel<<<gblk(NN), 256, GEMM_SMEM>>>(pstack + (size_t)b * NN * DD, nullptr,
            key_W + (size_t)b * DD * DD, nullptr, nullptr, key_b + (size_t)b * DD,
            nullptr, NN, 0, 0, pQ, plog, b);
    }
    softmax_fuse_kernel<<<APPLY_GRID, 256>>>(plog, pstack, ph);

    // final: relu(Fused @ (fuse_W@refine_W) + combined bias)
    gemm_kernel<<<gblk(NN), 256, GEMM_SMEM>>>(ph, nullptr, pWc,
        nullptr, nullptr, pbc, out, NN, 1, 0, nullptr, nullptr, 0);
}

// round 5
// speedup vs baseline: 1.4007x; 1.2147x over previous
#include <cuda_runtime.h>
#include <cuda_bf16.h>
#include <cstddef>

// ---------------- problem constants ----------------
constexpr int NUSER = 100000;
constexpr int NITEM = 50000;
constexpr int NN    = 150000;   // total nodes
constexpr int DD    = 128;
constexpr int BB    = 3;
constexpr int LL    = 2;
constexpr int EE    = 1500000;
constexpr float BN_EPS = 1e-5f;
constexpr int SEGS  = BB * NN;                 // 450000 (b,dst) segments
constexpr int SCAN_BLOCKS = (SEGS + 1023) / 1024;   // 440

typedef unsigned long long ull;

// ---------------- device scratch (no allocation allowed) ----------------
__device__ float g_x[(size_t)NN * DD];           // initial node features
__device__ float g_h[(size_t)NN * DD];           // current hidden
__device__ float g_agg[(size_t)NN * DD];         // aggregation scratch
__device__ float g_Q[(size_t)NN * DD];           // attention query
__device__ float g_stack[(size_t)BB * NN * DD];  // per-behavior outputs
__device__ float g_rd[SEGS];                     // 1/max(deg,1)
__device__ float g_logits[(size_t)NN * BB];
__device__ float g_colstat[2 * DD];              // BN column sum / sumsq
__device__ float g_bnsc[DD], g_bnsh[DD];         // BN fused scale / shift
__device__ float g_Wc[DD * DD];                  // fuse_W @ refine_W
__device__ float g_bc[DD];                       // fuse_b @ refine_W + refine_b
__device__ int   g_icnt[SEGS];                   // degree per (b,dst)
__device__ int   g_coff[SEGS];                   // CSR offsets (exclusive scan)
__device__ int   g_ccur[SEGS];                   // fill cursors
__device__ int   g_bsum[SCAN_BLOCKS + 8];        // scan block sums
__device__ int   g_bsumoff[SCAN_BLOCKS + 8];     // scanned block sums
__device__ int   g_csrc[EE];                     // CSR src lists

// ---------------- f32x2 packed-FMA helpers ----------------
#define FFMA2(d, a, b) \
    asm("fma.rn.f32x2 %0, %1, %2, %3;" : "=l"(d) : "l"(a), "l"(b), "l"(d))
#define PACKDUP(d, f) do { unsigned _u = __float_as_uint(f); \
    asm("mov.b64 %0, {%1, %2};" : "=l"(d) : "r"(_u), "r"(_u)); } while (0)
#define UNPK(lo, hi, d) do { unsigned _l, _h; \
    asm("mov.b64 {%0, %1}, %2;" : "=r"(_l), "=r"(_h) : "l"(d)); \
    lo = __uint_as_float(_l); hi = __uint_as_float(_h); } while (0)

// ---------------- small helpers ----------------
__global__ void zero_int_kernel(int4* p, int n4) {
    int i = blockIdx.x * blockDim.x + threadIdx.x;
    int stride = gridDim.x * blockDim.x;
    int4 z = make_int4(0, 0, 0, 0);
    for (; i < n4; i += stride) p[i] = z;
}

__global__ void zero_stats_kernel() {
    if (threadIdx.x < 2 * DD) g_colstat[threadIdx.x] = 0.f;
}

// degree count per (behavior, dst)
__global__ void count_kernel(const int* __restrict__ ei, const int* __restrict__ et) {
    int e = blockIdx.x * blockDim.x + threadIdx.x;
    if (e >= EE) return;
    int t = et[e];
    int d = ei[EE + e];
    atomicAdd(&g_icnt[t * NN + d], 1);
}

// ---- exclusive scan over g_icnt (3 kernels) ----
__global__ void scan1_kernel() {
    __shared__ int s[1024];
    int gid = blockIdx.x * 1024 + threadIdx.x;
    int v = (gid < SEGS) ? g_icnt[gid] : 0;
    s[threadIdx.x] = v;
    __syncthreads();
#pragma unroll
    for (int off = 1; off < 1024; off <<= 1) {
        int t = (threadIdx.x >= off) ? s[threadIdx.x - off] : 0;
        __syncthreads();
        s[threadIdx.x] += t;
        __syncthreads();
    }
    if (gid < SEGS) g_coff[gid] = s[threadIdx.x] - v;   // exclusive
    if (threadIdx.x == 1023) g_bsum[blockIdx.x] = s[1023];
}

__global__ void scan2_kernel() {
    if (threadIdx.x == 0) {
        int a = 0;
        for (int i = 0; i < SCAN_BLOCKS; ++i) { g_bsumoff[i] = a; a += g_bsum[i]; }
    }
}

__global__ void scan3_kernel() {
    int gid = blockIdx.x * 1024 + threadIdx.x;
    if (gid >= SEGS) return;
    int o = g_coff[gid] + g_bsumoff[gid >> 10];
    g_coff[gid] = o;
    g_ccur[gid] = o;
    g_rd[gid] = 1.0f / fmaxf((float)g_icnt[gid], 1.0f);
}

// fill CSR src lists
__global__ void fill_kernel(const int* __restrict__ ei, const int* __restrict__ et) {
    int e = blockIdx.x * blockDim.x + threadIdx.x;
    if (e >= EE) return;
    int t = et[e];
    int d = ei[EE + e];
    int pos = atomicAdd(&g_ccur[t * NN + d], 1);
    g_csrc[pos] = ei[e];
}

// warp-per-dst gather: agg[d] = (1/deg) * sum_{s in N_b(d)} h[s]
__global__ void gather_kernel(const float* __restrict__ h, float* __restrict__ agg, int b) {
    int w = blockIdx.x * (blockDim.x >> 5) + (threadIdx.x >> 5);
    if (w >= NN) return;
    int lane = threadIdx.x & 31;
    int seg = b * NN + w;
    int lo = g_coff[seg];
    int deg = g_icnt[seg];
    float4 acc = make_float4(0.f, 0.f, 0.f, 0.f);
    const float4* h4 = reinterpret_cast<const float4*>(h);
    for (int j0 = 0; j0 < deg; j0 += 32) {
        int rem = deg - j0;
        int m = rem < 32 ? rem : 32;
        int idx = (lane < m) ? g_csrc[lo + j0 + lane] : 0;
        for (int j = 0; j < m; ++j) {
            int s = __shfl_sync(0xFFFFFFFFu, idx, j);
            float4 v = h4[(size_t)s * 32 + lane];
            acc.x += v.x; acc.y += v.y; acc.z += v.z; acc.w += v.w;
        }
    }
    float r = g_rd[seg];
    acc.x *= r; acc.y *= r; acc.z *= r; acc.w *= r;
    reinterpret_cast<float4*>(agg)[(size_t)w * 32 + lane] = acc;
}

// ---------------- FFMA2 tiled GEMM ----------------
// C[M,128] = A@W (+ A2@W2) + bias, optional relu.
// Optional fused epilogues: BN column stats (do_colstat) or Q-dot logits (Qdot).
constexpr int GEMM_SMEM = (128 * 64 + 128 * 128) * 4;   // 96 KB

__global__ __launch_bounds__(256) void gemm_kernel(
    const float* __restrict__ A,
    const float* __restrict__ W,
    const float* __restrict__ A2, const float* __restrict__ W2,
    const float* __restrict__ bias,
    float* __restrict__ C, int M, int relu, int do_colstat,
    const float* __restrict__ Qdot, float* __restrict__ logits, int bidx)
{
    extern __shared__ float sm[];
    float* AsT = sm;                 // [128][64] k-major
    float* Ws  = sm + 128 * 64;      // [128][128]
    int tid = threadIdx.x;
    int tx = tid & 15, ty = tid >> 4;
    int row0 = blockIdx.x * 64;

    ull acc[4][4];
#pragma unroll
    for (int i = 0; i < 4; i++)
#pragma unroll
        for (int p = 0; p < 4; p++) acc[i][p] = 0ull;

    for (int pass = 0; pass < 2; ++pass) {
        const float* Ap = pass ? A2 : A;
        const float* Wp = pass ? W2 : W;
        if (Ap == nullptr) break;
        if (pass) __syncthreads();   // finish reading previous tiles

        // load W tile (coalesced, conflict-free STS.128)
#pragma unroll
        for (int i = 0; i < 16; ++i) {
            int idx = tid + i * 256;
            reinterpret_cast<float4*>(Ws)[idx] = reinterpret_cast<const float4*>(Wp)[idx];
        }
        // load A tile transposed
#pragma unroll
        for (int i = 0; i < 8; ++i) {
            int idx = tid + i * 256;
            int r = idx & 63, c4 = idx >> 6;     // c4 in 0..31
            int gr = row0 + r;
            float4 v = make_float4(0.f, 0.f, 0.f, 0.f);
            if (gr < M) v = reinterpret_cast<const float4*>(Ap)[(size_t)gr * 32 + c4];
            int c = c4 * 4;
            AsT[(c + 0) * 64 + r] = v.x;
            AsT[(c + 1) * 64 + r] = v.y;
            AsT[(c + 2) * 64 + r] = v.z;
            AsT[(c + 3) * 64 + r] = v.w;
        }
        __syncthreads();

#pragma unroll 8
        for (int k = 0; k < DD; ++k) {
            ulonglong2 w0 = *reinterpret_cast<const ulonglong2*>(Ws + k * 128 + tx * 4);
            ulonglong2 w1 = *reinterpret_cast<const ulonglong2*>(Ws + k * 128 + 64 + tx * 4);
            float4 av = *reinterpret_cast<const float4*>(AsT + k * 64 + ty * 4);
            ull aa0, aa1, aa2, aa3;
            PACKDUP(aa0, av.x); PACKDUP(aa1, av.y);
            PACKDUP(aa2, av.z); PACKDUP(aa3, av.w);
            FFMA2(acc[0][0], aa0, w0.x); FFMA2(acc[0][1], aa0, w0.y);
            FFMA2(acc[0][2], aa0, w1.x); FFMA2(acc[0][3], aa0, w1.y);
            FFMA2(acc[1][0], aa1, w0.x); FFMA2(acc[1][1], aa1, w0.y);
            FFMA2(acc[1][2], aa1, w1.x); FFMA2(acc[1][3], aa1, w1.y);
            FFMA2(acc[2][0], aa2, w0.x); FFMA2(acc[2][1], aa2, w0.y);
            FFMA2(acc[2][2], aa2, w1.x); FFMA2(acc[2][3], aa2, w1.y);
            FFMA2(acc[3][0], aa3, w0.x); FFMA2(acc[3][1], aa3, w0.y);
            FFMA2(acc[3][2], aa3, w1.x); FFMA2(acc[3][3], aa3, w1.y);
        }
    }
    __syncthreads();   // smem free for epilogue reuse

    // unpack + bias + relu
    float out[4][8];
    float4 b0 = make_float4(0.f, 0.f, 0.f, 0.f), b1 = b0;
    if (bias) {
        b0 = reinterpret_cast<const float4*>(bias)[tx];
        b1 = reinterpret_cast<const float4*>(bias)[16 + tx];
    }
#pragma unroll
    for (int i = 0; i < 4; i++) {
        UNPK(out[i][0], out[i][1], acc[i][0]);
        UNPK(out[i][2], out[i][3], acc[i][1]);
        UNPK(out[i][4], out[i][5], acc[i][2]);
        UNPK(out[i][6], out[i][7], acc[i][3]);
        out[i][0] += b0.x; out[i][1] += b0.y; out[i][2] += b0.z; out[i][3] += b0.w;
        out[i][4] += b1.x; out[i][5] += b1.y; out[i][6] += b1.z; out[i][7] += b1.w;
        if (relu)
#pragma unroll
            for (int j = 0; j < 8; j++) out[i][j] = fmaxf(out[i][j], 0.f);
    }

    if (C) {
#pragma unroll
        for (int i = 0; i < 4; i++) {
            int gr = row0 + ty * 4 + i;
            if (gr >= M) continue;
            float4 lo = make_float4(out[i][0], out[i][1], out[i][2], out[i][3]);
            float4 hi = make_float4(out[i][4], out[i][5], out[i][6], out[i][7]);
            reinterpret_cast<float4*>(C)[(size_t)gr * 32 + tx] = lo;
            reinterpret_cast<float4*>(C)[(size_t)gr * 32 + 16 + tx] = hi;
        }
    }

    if (do_colstat) {
        float* sc = sm;           // 256 floats: [0..127]=sum, [128..255]=sumsq
        sc[tid] = 0.f;
        __syncthreads();
#pragma unroll
        for (int j = 0; j < 8; j++) {
            int col = (j < 4) ? (tx * 4 + j) : (64 + tx * 4 + (j - 4));
            float s = 0.f, q = 0.f;
#pragma unroll
            for (int i = 0; i < 4; i++) {
                int gr = row0 + ty * 4 + i;
                if (gr < M) { float v = out[i][j]; s += v; q += v * v; }
            }
            atomicAdd(&sc[col], s);
            atomicAdd(&sc[128 + col], q);
        }
        __syncthreads();
        if (tid < 128) {
            atomicAdd(&g_colstat[tid], sc[tid]);
            atomicAdd(&g_colstat[128 + tid], sc[128 + tid]);
        }
    }

    if (Qdot) {
        float* sd = sm;           // [64][16]
#pragma unroll
        for (int i = 0; i < 4; i++) {
            int gr = row0 + ty * 4 + i;
            float p = 0.f;
            if (gr < M) {
                float4 q0 = reinterpret_cast<const float4*>(Qdot)[(size_t)gr * 32 + tx];
                float4 q1 = reinterpret_cast<const float4*>(Qdot)[(size_t)gr * 32 + 16 + tx];
                p = out[i][0] * q0.x + out[i][1] * q0.y + out[i][2] * q0.z + out[i][3] * q0.w
                  + out[i][4] * q1.x + out[i][5] * q1.y + out[i][6] * q1.z + out[i][7] * q1.w;
            }
            sd[(ty * 4 + i) * 16 + tx] = p;
        }
        __syncthreads();
        if (tid < 64) {
            float s = 0.f;
#pragma unroll
            for (int j = 0; j < 16; j++) s += sd[tid * 16 + j];
            int gr = row0 + tid;
            if (gr < M) logits[(size_t)gr * BB + bidx] = s;
        }
    }
}

// ---------------- BatchNorm finalize / apply ----------------
__global__ void bn_finalize_kernel(const float* __restrict__ gamma, const float* __restrict__ beta) {
    int c = threadIdx.x;
    if (c >= DD) return;
    float mu = g_colstat[c] * (1.0f / NN);
    float var = g_colstat[DD + c] * (1.0f / NN) - mu * mu;
    float sc = gamma[c] * rsqrtf(var + BN_EPS);
    g_bnsc[c] = sc;
    g_bnsh[c] = beta[c] - mu * sc;
}

// mode 0: h = relu(norm(h)) in place.  mode 1: outstack = x + norm(h)
__global__ void bn_apply_kernel(float* __restrict__ h, const float* __restrict__ x,
                                float* __restrict__ outstack, int mode) {
    int idx = blockIdx.x * blockDim.x + threadIdx.x;       // over NN*32 float4s
    if (idx >= NN * 32) return;
    int c4 = (idx & 31) * 4;
    float4 v = reinterpret_cast<float4*>(h)[idx];
    float4 o;
    o.x = v.x * g_bnsc[c4 + 0] + g_bnsh[c4 + 0];
    o.y = v.y * g_bnsc[c4 + 1] + g_bnsh[c4 + 1];
    o.z = v.z * g_bnsc[c4 + 2] + g_bnsh[c4 + 2];
    o.w = v.w * g_bnsc[c4 + 3] + g_bnsh[c4 + 3];
    if (mode == 0) {
        o.x = fmaxf(o.x, 0.f); o.y = fmaxf(o.y, 0.f);
        o.z = fmaxf(o.z, 0.f); o.w = fmaxf(o.w, 0.f);
        reinterpret_cast<float4*>(h)[idx] = o;
    } else {
        float4 xv = reinterpret_cast<const float4*>(x)[idx];
        o.x += xv.x; o.y += xv.y; o.z += xv.z; o.w += xv.w;
        reinterpret_cast<float4*>(outstack)[idx] = o;
    }
}

// ---------------- softmax + weighted fuse ----------------
__global__ void softmax_fuse_kernel(const float* __restrict__ logits,
                                    const float* __restrict__ stack,
                                    float* __restrict__ out) {
    int idx = blockIdx.x * blockDim.x + threadIdx.x;   // over NN*32 float4s
    if (idx >= NN * 32) return;
    int n = idx >> 5;
    float l0 = logits[(size_t)n * 3 + 0];
    float l1 = logits[(size_t)n * 3 + 1];
    float l2 = logits[(size_t)n * 3 + 2];
    float m = fmaxf(l0, fmaxf(l1, l2));
    float e0 = __expf(l0 - m), e1 = __expf(l1 - m), e2 = __expf(l2 - m);
    float inv = 1.0f / (e0 + e1 + e2);
    float w0 = e0 * inv, w1 = e1 * inv, w2 = e2 * inv;
    float4 s0 = reinterpret_cast<const float4*>(stack)[idx];
    float4 s1 = reinterpret_cast<const float4*>(stack + (size_t)NN * DD)[idx];
    float4 s2 = reinterpret_cast<const float4*>(stack + (size_t)2 * NN * DD)[idx];
    float4 o;
    o.x = w0 * s0.x + w1 * s1.x + w2 * s2.x;
    o.y = w0 * s0.y + w1 * s1.y + w2 * s2.y;
    o.z = w0 * s0.z + w1 * s1.z + w2 * s2.z;
    o.w = w0 * s0.w + w1 * s1.w + w2 * s2.w;
    reinterpret_cast<float4*>(out)[idx] = o;
}

// bc = fuse_b @ refine_W + refine_b
__global__ void bias_combine_kernel(const float* __restrict__ fuse_b,
                                    const float* __restrict__ refine_W,
                                    const float* __restrict__ refine_b) {
    int c = threadIdx.x;
    if (c >= DD) return;
    float s = refine_b[c];
    for (int k = 0; k < DD; ++k) s += fuse_b[k] * refine_W[k * DD + c];
    g_bc[c] = s;
}

// ---------------- host launch ----------------
static inline int gblk(int m) { return (m + 63) / 64; }

extern "C" void kernel_launch(void* const* d_in, const int* in_sizes, int n_in,
                              void* d_out, int out_size) {
    const int*   ei          = (const int*)d_in[0];    // edge_index [2,E]
    const int*   et          = (const int*)d_in[1];    // edge_type [E]
    const float* item_feats  = (const float*)d_in[2];
    const float* user_emb    = (const float*)d_in[3];
    const float* user_proj_W = (const float*)d_in[4];
    const float* user_proj_b = (const float*)d_in[5];
    const float* item_proj_W = (const float*)d_in[6];
    const float* item_proj_b = (const float*)d_in[7];
    const float* sage_Wl     = (const float*)d_in[8];  // [B,L,D,D]
    const float* sage_bl     = (const float*)d_in[9];  // [B,L,D]
    const float* sage_Wr     = (const float*)d_in[10]; // [B,L,D,D]
    const float* bn_gamma    = (const float*)d_in[11]; // [B,L,D]
    const float* bn_beta     = (const float*)d_in[12];
    const float* query_W     = (const float*)d_in[13];
    const float* query_b     = (const float*)d_in[14];
    const float* key_W       = (const float*)d_in[15]; // [B,D,D]
    const float* key_b       = (const float*)d_in[16]; // [B,D]
    const float* fuse_W      = (const float*)d_in[17];
    const float* fuse_b      = (const float*)d_in[18];
    const float* refine_W    = (const float*)d_in[19];
    const float* refine_b    = (const float*)d_in[20];
    float* out = (float*)d_out;
    (void)in_sizes; (void)n_in; (void)out_size;

    float *px, *ph, *pagg, *pQ, *pstack, *plog, *pWc, *pbc;
    int *picnt;
    cudaGetSymbolAddress((void**)&px,     g_x);
    cudaGetSymbolAddress((void**)&ph,     g_h);
    cudaGetSymbolAddress((void**)&pagg,   g_agg);
    cudaGetSymbolAddress((void**)&pQ,     g_Q);
    cudaGetSymbolAddress((void**)&pstack, g_stack);
    cudaGetSymbolAddress((void**)&plog,   g_logits);
    cudaGetSymbolAddress((void**)&pWc,    g_Wc);
    cudaGetSymbolAddress((void**)&pbc,    g_bc);
    cudaGetSymbolAddress((void**)&picnt,  g_icnt);

    cudaFuncSetAttribute(gemm_kernel, cudaFuncAttributeMaxDynamicSharedMemorySize, GEMM_SMEM);

    const int NV4 = NN * 32;
    const int APPLY_GRID = (NV4 + 255) / 256;
    const int GATHER_GRID = (NN + 7) / 8;       // 8 warps / block

    // ---- edge preprocessing: CSR by (behavior, dst) ----
    zero_int_kernel<<<256, 256>>>((int4*)picnt, SEGS / 4);
    count_kernel<<<(EE + 255) / 256, 256>>>(ei, et);
    scan1_kernel<<<SCAN_BLOCKS, 1024>>>();
    scan2_kernel<<<1, 32>>>();
    scan3_kernel<<<SCAN_BLOCKS, 1024>>>();
    fill_kernel<<<(EE + 255) / 256, 256>>>(ei, et);

    // precombine fuse+refine (no nonlinearity between them)
    gemm_kernel<<<gblk(DD), 256, GEMM_SMEM>>>(fuse_W, refine_W,
        nullptr, nullptr, nullptr, pWc, DD, 0, 0, nullptr, nullptr, 0);
    bias_combine_kernel<<<1, 128>>>(fuse_b, refine_W, refine_b);

    // initial features x = [user_emb@Wu + bu ; item_feats@Wi + bi]
    gemm_kernel<<<gblk(NUSER), 256, GEMM_SMEM>>>(user_emb, user_proj_W,
        nullptr, nullptr, user_proj_b, px, NUSER, 0, 0, nullptr, nullptr, 0);
    gemm_kernel<<<gblk(NITEM), 256, GEMM_SMEM>>>(item_feats, item_proj_W,
        nullptr, nullptr, item_proj_b, px + (size_t)NUSER * DD, NITEM, 0, 0, nullptr, nullptr, 0);

    for (int b = 0; b < BB; ++b) {
        const float* hin = px;
        for (int l = 0; l < LL; ++l) {
            int bl = b * LL + l;
            gather_kernel<<<GATHER_GRID, 256>>>(hin, pagg, b);
            zero_stats_kernel<<<1, 256>>>();
            // h = agg@Wl + h@Wr + bl   (+ fused BN column stats)
            gemm_kernel<<<gblk(NN), 256, GEMM_SMEM>>>(pagg,
                sage_Wl + (size_t)bl * DD * DD, hin, sage_Wr + (size_t)bl * DD * DD,
                sage_bl + (size_t)bl * DD, ph, NN, 0, 1, nullptr, nullptr, 0);
            bn_finalize_kernel<<<1, 128>>>(bn_gamma + (size_t)bl * DD, bn_beta + (size_t)bl * DD);
            if (l < LL - 1) {
                bn_apply_kernel<<<APPLY_GRID, 256>>>(ph, px, nullptr, 0);       // relu in place
            } else {
                bn_apply_kernel<<<APPLY_GRID, 256>>>(ph, px,
                    pstack + (size_t)b * NN * DD, 1);                            // residual
            }
            hin = ph;
        }
    }

    // attention: Q, then K-GEMMs with fused Q-dot (no K materialization)
    gemm_kernel<<<gblk(NN), 256, GEMM_SMEM>>>(px, query_W,
        nullptr, nullptr, query_b, pQ, NN, 0, 0, nullptr, nullptr, 0);
    for (int b = 0; b < BB; ++b) {
        gemm_kernel<<<gblk(NN), 256, GEMM_SMEM>>>(pstack + (size_t)b * NN * DD,
            key_W + (size_t)b * DD * DD, nullptr, nullptr, key_b + (size_t)b * DD,
            nullptr, NN, 0, 0, pQ, plog, b);
    }
    softmax_fuse_kernel<<<APPLY_GRID, 256>>>(plog, pstack, ph);

    // final: relu(Fused @ (fuse_W@refine_W) + combined bias)
    gemm_kernel<<<gblk(NN), 256, GEMM_SMEM>>>(ph, pWc,
        nullptr, nullptr, pbc, out, NN, 1, 0, nullptr, nullptr, 0);
}